// round 1
// baseline (speedup 1.0000x reference)
#include <cuda_runtime.h>

// CropAndResize: image (8,256,200,200) f32 NCHW, boxes (512,4) [y1,x1,y2,x2],
// box_indices (512,) int32 -> out (512,256,14,14) f32.
// Bilinear crop-and-resize, extrapolation value 0.

#define IH 200
#define IW 200
#define CROP 14
#define NCH 256
#define NBOX 512
#define PLANE (IH * IW)
#define POS (CROP * CROP)          // 196
#define CCHUNK 64                  // channels per block
#define NCHUNKS (NCH / CCHUNK)     // 4
#define TPB 256
#define ITERS (CCHUNK * POS / TPB) // 49

__global__ __launch_bounds__(TPB) void crop_resize_kernel(
    const float* __restrict__ image,
    const float* __restrict__ boxes,
    const int*   __restrict__ box_idx,
    float*       __restrict__ out)
{
    __shared__ int   sy0[CROP], sy1[CROP], sx0[CROP], sx1[CROP];
    __shared__ float sly[CROP], slx[CROP];
    __shared__ unsigned svy[CROP], svx[CROP];
    __shared__ const float* splane;

    const int n      = blockIdx.x / NCHUNKS;   // box index (chunks adjacent -> L2 reuse)
    const int cchunk = blockIdx.x % NCHUNKS;
    const int tid    = threadIdx.x;

    // Per-box interpolation coefficients: threads 0..13 do x-axis, 14..27 y-axis.
    if (tid < 2 * CROP) {
        const bool isx = (tid < CROP);
        const int  k   = isx ? tid : tid - CROP;
        const float a1 = boxes[n * 4 + (isx ? 1 : 0)];
        const float a2 = boxes[n * 4 + (isx ? 3 : 2)];
        const float D  = isx ? (float)(IW - 1) : (float)(IH - 1);
        const float scale = (a2 - a1) * D * (1.0f / (CROP - 1));
        const float v  = a1 * D + (float)k * scale;
        const unsigned valid = (v >= 0.0f) && (v <= D);
        const float fl = floorf(v);
        const float ce = ceilf(v);
        const float l  = v - fl;
        const int i0 = (int)fminf(fmaxf(fl, 0.0f), D);
        const int i1 = (int)fminf(fmaxf(ce, 0.0f), D);
        if (isx) { sx0[k] = i0; sx1[k] = i1; slx[k] = l; svx[k] = valid; }
        else     { sy0[k] = i0; sy1[k] = i1; sly[k] = l; svy[k] = valid; }
    }
    if (tid == 0) {
        const int b = box_idx[n];
        splane = image + (size_t)b * NCH * PLANE;
    }
    __syncthreads();

    const float* base = splane + (size_t)cchunk * CCHUNK * PLANE;
    float* outp = out + (size_t)n * NCH * POS + (size_t)cchunk * CCHUNK * POS;

    int i = tid;  // linear index over (c_local, pos) -> contiguous coalesced stores
    #pragma unroll 7
    for (int it = 0; it < ITERS; ++it, i += TPB) {
        const int c   = i / POS;
        const int pos = i - c * POS;
        const int r   = pos / CROP;
        const int col = pos - r * CROP;

        const float* pl = base + c * PLANE;
        const int y0 = sy0[r], y1 = sy1[r];
        const int x0 = sx0[col], x1 = sx1[col];

        const float tl = __ldg(pl + y0 * IW + x0);
        const float tr = __ldg(pl + y0 * IW + x1);
        const float bl = __ldg(pl + y1 * IW + x0);
        const float br = __ldg(pl + y1 * IW + x1);

        const float lx = slx[col], ly = sly[r];
        const float top = tl + (tr - tl) * lx;
        const float bot = bl + (br - bl) * lx;
        float val = top + (bot - top) * ly;
        if (!(svy[r] & svx[col])) val = 0.0f;

        outp[i] = val;
    }
}

extern "C" void kernel_launch(void* const* d_in, const int* in_sizes, int n_in,
                              void* d_out, int out_size)
{
    const float* image   = (const float*)d_in[0];
    const float* boxes   = (const float*)d_in[1];
    const int*   box_idx = (const int*)d_in[2];
    float*       out     = (float*)d_out;

    crop_resize_kernel<<<NBOX * NCHUNKS, TPB>>>(image, boxes, box_idx, out);
}

// round 2
// speedup vs baseline: 1.2991x; 1.2991x over previous
#include <cuda_runtime.h>

// CropAndResize: image (8,256,200,200) f32 NCHW, boxes (512,4) [y1,x1,y2,x2],
// box_indices (512,) int32 -> out (512,256,14,14) f32. Bilinear, extrap 0.
//
// R2: counting-sort boxes by image index + cchunk-major block ordering so that
// concurrently-resident CTAs share the same (image, channel-chunk) planes in L2.

#define IH 200
#define IW 200
#define CROP 14
#define NCH 256
#define NBOX 512
#define NIMG 8
#define PLANE (IH * IW)
#define POS (CROP * CROP)          // 196
#define CCHUNK 64                  // channels per block
#define NCHUNKS (NCH / CCHUNK)     // 4
#define TPB 256
#define ITERS (CCHUNK * POS / TPB) // 49

__device__ int d_perm[NBOX];       // box ids sorted by image index

__global__ __launch_bounds__(NBOX) void sort_boxes_kernel(
    const int* __restrict__ box_idx)
{
    __shared__ int cnt[NIMG];
    __shared__ int off[NIMG + 1];
    const int tid = threadIdx.x;
    if (tid < NIMG) cnt[tid] = 0;
    __syncthreads();
    const int b = box_idx[tid];
    atomicAdd(&cnt[b], 1);
    __syncthreads();
    if (tid == 0) {
        int s = 0;
        for (int i = 0; i < NIMG; ++i) { off[i] = s; s += cnt[i]; }
        off[NIMG] = s;
    }
    __syncthreads();
    const int pos = atomicAdd(&off[b], 1);   // order within bucket is irrelevant
    d_perm[pos] = tid;
}

__global__ __launch_bounds__(TPB) void crop_resize_kernel(
    const float* __restrict__ image,
    const float* __restrict__ boxes,
    const int*   __restrict__ box_idx,
    float*       __restrict__ out)
{
    __shared__ int   sy0[CROP], sy1[CROP], sx0[CROP], sx1[CROP];
    __shared__ float sly[CROP], slx[CROP];
    __shared__ unsigned svy[CROP], svx[CROP];
    __shared__ int sn;
    __shared__ const float* splane;

    // cchunk-major: all concurrent blocks share one channel chunk, boxes
    // grouped by image -> small L2 working set.
    const int cchunk = blockIdx.x / NBOX;
    const int spos   = blockIdx.x % NBOX;
    const int tid    = threadIdx.x;

    if (tid == 0) {
        const int n = d_perm[spos];
        sn = n;
        splane = image + (size_t)box_idx[n] * NCH * PLANE;
    }
    __syncthreads();
    const int n = sn;

    // Per-box interpolation coefficients: threads 0..13 x-axis, 14..27 y-axis.
    if (tid < 2 * CROP) {
        const bool isx = (tid < CROP);
        const int  k   = isx ? tid : tid - CROP;
        const float a1 = boxes[n * 4 + (isx ? 1 : 0)];
        const float a2 = boxes[n * 4 + (isx ? 3 : 2)];
        const float D  = isx ? (float)(IW - 1) : (float)(IH - 1);
        const float scale = (a2 - a1) * D * (1.0f / (CROP - 1));
        const float v  = a1 * D + (float)k * scale;
        const unsigned valid = (v >= 0.0f) && (v <= D);
        const float fl = floorf(v);
        const float ce = ceilf(v);
        const float l  = v - fl;
        const int i0 = (int)fminf(fmaxf(fl, 0.0f), D);
        const int i1 = (int)fminf(fmaxf(ce, 0.0f), D);
        if (isx) { sx0[k] = i0; sx1[k] = i1; slx[k] = l; svx[k] = valid; }
        else     { sy0[k] = i0; sy1[k] = i1; sly[k] = l; svy[k] = valid; }
    }
    __syncthreads();

    const float* base = splane + (size_t)cchunk * CCHUNK * PLANE;
    float* outp = out + (size_t)n * NCH * POS + (size_t)cchunk * CCHUNK * POS;

    int i = tid;  // linear over (c_local, pos) -> contiguous coalesced stores
    #pragma unroll 7
    for (int it = 0; it < ITERS; ++it, i += TPB) {
        const int c   = i / POS;
        const int pos = i - c * POS;
        const int r   = pos / CROP;
        const int col = pos - r * CROP;

        const float* pl = base + c * PLANE;
        const int y0 = sy0[r], y1 = sy1[r];
        const int x0 = sx0[col], x1 = sx1[col];

        const float tl = __ldg(pl + y0 * IW + x0);
        const float tr = __ldg(pl + y0 * IW + x1);
        const float bl = __ldg(pl + y1 * IW + x0);
        const float br = __ldg(pl + y1 * IW + x1);

        const float lx = slx[col], ly = sly[r];
        const float top = tl + (tr - tl) * lx;
        const float bot = bl + (br - bl) * lx;
        float val = top + (bot - top) * ly;
        if (!(svy[r] & svx[col])) val = 0.0f;

        outp[i] = val;
    }
}

extern "C" void kernel_launch(void* const* d_in, const int* in_sizes, int n_in,
                              void* d_out, int out_size)
{
    const float* image   = (const float*)d_in[0];
    const float* boxes   = (const float*)d_in[1];
    const int*   box_idx = (const int*)d_in[2];
    float*       out     = (float*)d_out;

    sort_boxes_kernel<<<1, NBOX>>>(box_idx);
    crop_resize_kernel<<<NCHUNKS * NBOX, TPB>>>(image, boxes, box_idx, out);
}

// round 3
// speedup vs baseline: 1.3555x; 1.0435x over previous
#include <cuda_runtime.h>

// CropAndResize: image (8,256,200,200) f32 NCHW, boxes (512,4) [y1,x1,y2,x2],
// box_indices (512,) int32 -> out (512,256,14,14) f32. Bilinear, extrap 0.
//
// R3: per-thread fixed crop position, loop over channels with pointer
// increments only. Box/chunk scheduling from R2 (counting-sort by image,
// cchunk-major blocks) kept for L2 locality. Streaming stores for output.

#define IH 200
#define IW 200
#define CROP 14
#define NCH 256
#define NBOX 512
#define NIMG 8
#define PLANE (IH * IW)
#define POS (CROP * CROP)          // 196
#define CCHUNK 64                  // channels per block
#define NCHUNKS (NCH / CCHUNK)     // 4
#define TPB (2 * POS)              // 392: threads 0..195 -> c0=0, 196..391 -> c0=1
#define CITERS (CCHUNK / 2)        // 32 channels per thread

__device__ int d_perm[NBOX];       // box ids sorted by image index

__global__ __launch_bounds__(NBOX) void sort_boxes_kernel(
    const int* __restrict__ box_idx)
{
    __shared__ int cnt[NIMG];
    __shared__ int off[NIMG + 1];
    const int tid = threadIdx.x;
    if (tid < NIMG) cnt[tid] = 0;
    __syncthreads();
    const int b = box_idx[tid];
    atomicAdd(&cnt[b], 1);
    __syncthreads();
    if (tid == 0) {
        int s = 0;
        for (int i = 0; i < NIMG; ++i) { off[i] = s; s += cnt[i]; }
        off[NIMG] = s;
    }
    __syncthreads();
    const int pos = atomicAdd(&off[b], 1);   // bucket-internal order irrelevant
    d_perm[pos] = tid;
}

__global__ __launch_bounds__(TPB) void crop_resize_kernel(
    const float* __restrict__ image,
    const float* __restrict__ boxes,
    const int*   __restrict__ box_idx,
    float*       __restrict__ out)
{
    __shared__ int   sy0[CROP], sy1[CROP], sx0[CROP], sx1[CROP];
    __shared__ float sly[CROP], slx[CROP];
    __shared__ unsigned svy[CROP], svx[CROP];
    __shared__ int sn;
    __shared__ const float* splane;

    const int cchunk = blockIdx.x / NBOX;   // cchunk-major: concurrent blocks
    const int spos   = blockIdx.x % NBOX;   // share a chunk, grouped by image
    const int tid    = threadIdx.x;

    if (tid == 0) {
        const int n = d_perm[spos];
        sn = n;
        splane = image + (size_t)box_idx[n] * NCH * PLANE;
    }
    __syncthreads();
    const int n = sn;

    // Per-box interpolation coefficients: threads 0..13 x-axis, 14..27 y-axis.
    if (tid < 2 * CROP) {
        const bool isx = (tid < CROP);
        const int  k   = isx ? tid : tid - CROP;
        const float a1 = boxes[n * 4 + (isx ? 1 : 0)];
        const float a2 = boxes[n * 4 + (isx ? 3 : 2)];
        const float D  = isx ? (float)(IW - 1) : (float)(IH - 1);
        const float scale = (a2 - a1) * D * (1.0f / (CROP - 1));
        const float v  = a1 * D + (float)k * scale;
        const unsigned valid = (v >= 0.0f) && (v <= D);
        const float fl = floorf(v);
        const float ce = ceilf(v);
        const float l  = v - fl;
        const int i0 = (int)fminf(fmaxf(fl, 0.0f), D);
        const int i1 = (int)fminf(fmaxf(ce, 0.0f), D);
        if (isx) { sx0[k] = i0; sx1[k] = i1; slx[k] = l; svx[k] = valid; }
        else     { sy0[k] = i0; sy1[k] = i1; sly[k] = l; svy[k] = valid; }
    }
    __syncthreads();

    // Decode once: c0 in {0,1}, pos in [0,196)
    const int c0  = (tid >= POS) ? 1 : 0;
    const int pos = tid - c0 * POS;
    const int r   = pos / CROP;
    const int col = pos - r * CROP;

    const int y0 = sy0[r], y1 = sy1[r];
    const int x0 = sx0[col], x1 = sx1[col];
    const float lx = slx[col], ly = sly[r];
    const bool valid = (svy[r] & svx[col]) != 0;

    const int o_tl = y0 * IW + x0;
    const int o_tr = y0 * IW + x1;
    const int o_bl = y1 * IW + x0;
    const int o_br = y1 * IW + x1;

    const float* pl = splane + (size_t)cchunk * CCHUNK * PLANE + (size_t)c0 * PLANE;
    float* outp = out + (size_t)n * NCH * POS + (size_t)cchunk * CCHUNK * POS
                      + (size_t)c0 * POS + pos;

    if (valid) {
        #pragma unroll 4
        for (int it = 0; it < CITERS; ++it) {
            const float tl = __ldg(pl + o_tl);
            const float tr = __ldg(pl + o_tr);
            const float bl = __ldg(pl + o_bl);
            const float br = __ldg(pl + o_br);
            const float top = tl + (tr - tl) * lx;
            const float bot = bl + (br - bl) * lx;
            const float val = top + (bot - top) * ly;
            __stcs(outp, val);
            pl   += 2 * PLANE;
            outp += 2 * POS;
        }
    } else {
        #pragma unroll 8
        for (int it = 0; it < CITERS; ++it) {
            __stcs(outp, 0.0f);
            outp += 2 * POS;
        }
    }
}

extern "C" void kernel_launch(void* const* d_in, const int* in_sizes, int n_in,
                              void* d_out, int out_size)
{
    const float* image   = (const float*)d_in[0];
    const float* boxes   = (const float*)d_in[1];
    const int*   box_idx = (const int*)d_in[2];
    float*       out     = (float*)d_out;

    sort_boxes_kernel<<<1, NBOX>>>(box_idx);
    crop_resize_kernel<<<NCHUNKS * NBOX, TPB>>>(image, boxes, box_idx, out);
}